// round 6
// baseline (speedup 1.0000x reference)
#include <cuda_runtime.h>
#include <math.h>

// RandomElasticDeformation3D — staged-f32 flow pipeline, one simple kernel per
// stage (mimic XLA's per-stage f32 rounding), then fused trilinear/nearest warp.
//
// flow = ALPHA * gaussW(gaussH(gaussD(resizeW(resizeH(resizeD(coarse))))))
// every stage rounds to f32; contractions are ascending-index fma chains.
// Gaussian: 16 taps, pad_lo = 7, pad_hi = 8  (y[n] = sum_t k[t] x[n+t-7]).

#define DV 128
#define NVOX (DV * DV * DV)
#define IMG_FLOATS_PER_B (NVOX * 4)
#define ROWF (DV * 3)                       // 384 floats per (b,d,h) row

static __device__ float4 g_A[DV];           // cubic resize rows (128 x 4)
static __device__ float  g_G[16];           // gaussian taps
static __device__ float  g_RD[2 * DV * 4 * 4 * 3];          // [b,d,j,k,c]
static __device__ float  g_RH[2 * DV * DV * 4 * 3];         // [b,d,h,k,c]
static __device__ float  g_R3[(size_t)2 * DV * DV * DV * 3]; // [b,d,h,w,c] resized
static __device__ float  g_F1[(size_t)2 * DV * DV * DV * 3]; // after gauss D
static __device__ float  g_F2[(size_t)2 * DV * DV * DV * 3]; // after gauss H

// ---------------------------------------------------------------------------
// Weights. Cubic: f32 jax-style (exact dyadic sample coords, Keys a=-0.5 with
// non-fused mul/add, sequential normalization sum, f32 divide). Gaussian:
// numpy double pipeline cast to f32.
// ---------------------------------------------------------------------------
__device__ __forceinline__ float keys_cubic_f32(float x) {
    float o = __fadd_rn(__fmul_rn(__fmul_rn(__fadd_rn(__fmul_rn(1.5f, x), -2.5f), x), x), 1.0f);
    if (x >= 1.0f)
        o = __fadd_rn(__fmul_rn(__fadd_rn(__fmul_rn(__fadd_rn(__fmul_rn(-0.5f, x), 2.5f), x), -4.0f), x), 2.0f);
    if (x >= 2.0f) o = 0.0f;
    return o;
}

__global__ void precompute_weights_kernel() {
    const int n = threadIdx.x;
    if (n < 16) {
        double ks = 0.0;
        for (int t = 0; t < 16; ++t) {
            double ax = (double)(t - 7);
            ks += exp(-ax * ax / 12.5);
        }
        double axn = (double)(n - 7);
        g_G[n] = (float)(exp(-axn * axn / 12.5) / ks);
    }
    if (n < DV) {
        float s = __fadd_rn(__fmul_rn(__fadd_rn((float)n, 0.5f), 0.03125f), -0.5f);
        float wv[4];
#pragma unroll
        for (int i = 0; i < 4; ++i) wv[i] = keys_cubic_f32(fabsf(__fadd_rn(s, -(float)i)));
        float tot = __fadd_rn(__fadd_rn(__fadd_rn(wv[0], wv[1]), wv[2]), wv[3]);
        g_A[n] = make_float4(__fdiv_rn(wv[0], tot), __fdiv_rn(wv[1], tot),
                             __fdiv_rn(wv[2], tot), __fdiv_rn(wv[3], tot));
    }
}

// ---------------------------------------------------------------------------
// Resize along D: coarse[b,i,j,k,c] -> RD[b,d,j,k,c]
// ---------------------------------------------------------------------------
__global__ void resizeD_kernel(const float* __restrict__ coarse) {
    const int idx = blockIdx.x * blockDim.x + threadIdx.x;
    if (idx >= 2 * DV * 48) return;
    const int c = idx % 3;
    const int k = (idx / 3) % 4;
    const int j = (idx / 12) % 4;
    const int d = (idx / 48) % DV;
    const int b = idx / (48 * DV);
    const float4 A = g_A[d];
    const float Ai[4] = {A.x, A.y, A.z, A.w};
    float acc = 0.0f;
#pragma unroll
    for (int i = 0; i < 4; ++i)
        acc = fmaf(Ai[i], coarse[(((b * 4 + i) * 4 + j) * 4 + k) * 3 + c], acc);
    g_RD[idx] = acc;
}

// ---------------------------------------------------------------------------
// Resize along H: RD[b,d,j,k,c] -> RH[b,d,h,k,c]
// ---------------------------------------------------------------------------
__global__ void resizeH_kernel() {
    const int idx = blockIdx.x * blockDim.x + threadIdx.x;
    if (idx >= 2 * DV * DV * 12) return;
    const int c = idx % 3;
    const int k = (idx / 3) % 4;
    const int h = (idx / 12) % DV;
    const int d = (idx / (12 * DV)) % DV;
    const int b = idx / (12 * DV * DV);
    const float4 A = g_A[h];
    const float Aj[4] = {A.x, A.y, A.z, A.w};
    float acc = 0.0f;
#pragma unroll
    for (int j = 0; j < 4; ++j)
        acc = fmaf(Aj[j], g_RD[(((b * DV + d) * 4 + j) * 4 + k) * 3 + c], acc);
    g_RH[idx] = acc;
}

// ---------------------------------------------------------------------------
// Resize along W: RH[b,d,h,k,c] -> R3[b,d,h,w,c].  grid(h, d, b), 128 thr (w).
// ---------------------------------------------------------------------------
__global__ void __launch_bounds__(128)
resizeW_kernel() {
    const int w = threadIdx.x;
    const int h = blockIdx.x;
    const int d = blockIdx.y;
    const int b = blockIdx.z;
    __shared__ float rh[12];
    if (threadIdx.x < 12) rh[threadIdx.x] = g_RH[((b * DV + d) * DV + h) * 12 + threadIdx.x];
    __syncthreads();
    const float4 A = g_A[w];
    const float Ak[4] = {A.x, A.y, A.z, A.w};
    float* o = g_R3 + ((((size_t)b * DV + d) * DV + h) * DV + w) * 3;
#pragma unroll
    for (int c = 0; c < 3; ++c) {
        float acc = 0.0f;
#pragma unroll
        for (int k = 0; k < 4; ++k) acc = fmaf(Ak[k], rh[k * 3 + c], acc);
        o[c] = acc;
    }
}

// ---------------------------------------------------------------------------
// Gauss along D: R3 -> F1.  grid(h, b), 384 threads = (w,c) flattened.
// Per-thread 16-deep register shift window; win[t] == x[d + t - 7].
// ---------------------------------------------------------------------------
__global__ void __launch_bounds__(384)
gaussD_kernel() {
    const int tid = threadIdx.x;
    const int h = blockIdx.x;
    const int b = blockIdx.y;
    float G[16];
#pragma unroll
    for (int t = 0; t < 16; ++t) G[t] = g_G[t];

    const size_t base = ((size_t)b * DV * DV + h) * ROWF + tid;
    const size_t dstr = (size_t)DV * ROWF;

    float win[16];
#pragma unroll
    for (int t = 0; t < 7; ++t) win[t] = 0.0f;
#pragma unroll
    for (int t = 0; t < 9; ++t) win[7 + t] = g_R3[base + (size_t)t * dstr];

    for (int d = 0; d < DV; ++d) {
        float acc = 0.0f;
#pragma unroll
        for (int t = 0; t < 16; ++t) acc = fmaf(G[t], win[t], acc);
        g_F1[base + (size_t)d * dstr] = acc;
#pragma unroll
        for (int t = 0; t < 15; ++t) win[t] = win[t + 1];
        const int nxt = d + 9;
        win[15] = (nxt < DV) ? g_R3[base + (size_t)nxt * dstr] : 0.0f;
    }
}

// ---------------------------------------------------------------------------
// Gauss along H: F1 -> F2.  grid(d, b), 384 threads, walk h.
// ---------------------------------------------------------------------------
__global__ void __launch_bounds__(384)
gaussH_kernel() {
    const int tid = threadIdx.x;
    const int d = blockIdx.x;
    const int b = blockIdx.y;
    float G[16];
#pragma unroll
    for (int t = 0; t < 16; ++t) G[t] = g_G[t];

    const size_t base = ((size_t)b * DV + d) * DV * ROWF + tid;
    const size_t hstr = (size_t)ROWF;

    float win[16];
#pragma unroll
    for (int t = 0; t < 7; ++t) win[t] = 0.0f;
#pragma unroll
    for (int t = 0; t < 9; ++t) win[7 + t] = g_F1[base + (size_t)t * hstr];

    for (int h = 0; h < DV; ++h) {
        float acc = 0.0f;
#pragma unroll
        for (int t = 0; t < 16; ++t) acc = fmaf(G[t], win[t], acc);
        g_F2[base + (size_t)h * hstr] = acc;
#pragma unroll
        for (int t = 0; t < 15; ++t) win[t] = win[t + 1];
        const int nxt = h + 9;
        win[15] = (nxt < DV) ? g_F1[base + (size_t)nxt * hstr] : 0.0f;
    }
}

// ---------------------------------------------------------------------------
// Final: gauss along W (smem row, pad_lo=7 / pad_hi=8!) + *ALPHA, then
// trilinear image warp + nearest label warp.  grid(h, d, b), 128 threads (w).
// ---------------------------------------------------------------------------
__global__ void __launch_bounds__(128)
warp_kernel(const float4* __restrict__ img,
            const int*    __restrict__ lab,
            float4*       __restrict__ out_img,
            float*        __restrict__ out_lab) {
    const int w = threadIdx.x;
    const int h = blockIdx.x;
    const int d = blockIdx.y;
    const int b = blockIdx.z;

    // row stores wp = -7 .. 136 at index (wp+7)*3+c  =>  (DV+16)*3 = 432 floats.
    __shared__ float row[(DV + 16) * 3];
    if (threadIdx.x < 21) row[threadIdx.x] = 0.0f;                 // wp = -7..-1
    if (threadIdx.x < 27) row[(DV + 7) * 3 + threadIdx.x] = 0.0f;  // wp = 128..136
    {
        const float* src = g_F2 + (((size_t)b * DV + d) * DV + h) * ROWF;
#pragma unroll
        for (int t = 0; t < 3; ++t)
            row[21 + threadIdx.x + t * 128] = src[threadIdx.x + t * 128];
    }
    __syncthreads();

    float G[16];
#pragma unroll
    for (int t = 0; t < 16; ++t) G[t] = g_G[t];

    float fl[3];
#pragma unroll
    for (int c = 0; c < 3; ++c) {
        float acc = 0.0f;
#pragma unroll
        for (int t = 0; t < 16; ++t)
            acc = fmaf(G[t], row[(w + t) * 3 + c], acc);   // x[w+t-7]
        fl[c] = __fmul_rn(acc, 35.0f);
    }

    const float wd = __fadd_rn((float)d, fl[0]);
    const float wh = __fadd_rn((float)h, fl[1]);
    const float ww = __fadd_rn((float)w, fl[2]);

    // ---- trilinear image warp ----
    const float fdd = floorf(wd), fhh = floorf(wh), fww = floorf(ww);
    const float td = wd - fdd, th = wh - fhh, tw = ww - fww;

    const int d0 = min(max((int)fdd,     0), DV - 1);
    const int d1 = min(max((int)fdd + 1, 0), DV - 1);
    const int h0 = min(max((int)fhh,     0), DV - 1);
    const int h1 = min(max((int)fhh + 1, 0), DV - 1);
    const int w0 = min(max((int)fww,     0), DV - 1);
    const int w1 = min(max((int)fww + 1, 0), DV - 1);

    const float4* ib = img + (size_t)b * NVOX;
    const float4 v000 = ib[(d0 * DV + h0) * DV + w0];
    const float4 v001 = ib[(d0 * DV + h0) * DV + w1];
    const float4 v010 = ib[(d0 * DV + h1) * DV + w0];
    const float4 v011 = ib[(d0 * DV + h1) * DV + w1];
    const float4 v100 = ib[(d1 * DV + h0) * DV + w0];
    const float4 v101 = ib[(d1 * DV + h0) * DV + w1];
    const float4 v110 = ib[(d1 * DV + h1) * DV + w0];
    const float4 v111 = ib[(d1 * DV + h1) * DV + w1];

    const float omtw = 1.0f - tw, omth = 1.0f - th, omtd = 1.0f - td;
    float4 r;
    {
        float c00, c01, c10, c11, c0, c1;
        c00 = v000.x * omtw + v001.x * tw;  c01 = v010.x * omtw + v011.x * tw;
        c10 = v100.x * omtw + v101.x * tw;  c11 = v110.x * omtw + v111.x * tw;
        c0 = c00 * omth + c01 * th;  c1 = c10 * omth + c11 * th;
        r.x = c0 * omtd + c1 * td;
        c00 = v000.y * omtw + v001.y * tw;  c01 = v010.y * omtw + v011.y * tw;
        c10 = v100.y * omtw + v101.y * tw;  c11 = v110.y * omtw + v111.y * tw;
        c0 = c00 * omth + c01 * th;  c1 = c10 * omth + c11 * th;
        r.y = c0 * omtd + c1 * td;
        c00 = v000.z * omtw + v001.z * tw;  c01 = v010.z * omtw + v011.z * tw;
        c10 = v100.z * omtw + v101.z * tw;  c11 = v110.z * omtw + v111.z * tw;
        c0 = c00 * omth + c01 * th;  c1 = c10 * omth + c11 * th;
        r.z = c0 * omtd + c1 * td;
        c00 = v000.w * omtw + v001.w * tw;  c01 = v010.w * omtw + v011.w * tw;
        c10 = v100.w * omtw + v101.w * tw;  c11 = v110.w * omtw + v111.w * tw;
        c0 = c00 * omth + c01 * th;  c1 = c10 * omth + c11 * th;
        r.w = c0 * omtd + c1 * td;
    }

    const int vox = ((b * DV + d) * DV + h) * DV + w;
    out_img[vox] = r;

    // ---- nearest-neighbor label warp (rintf == jnp.round half-to-even) ----
    const int nd = min(max((int)rintf(wd), 0), DV - 1);
    const int nh = min(max((int)rintf(wh), 0), DV - 1);
    const int nw = min(max((int)rintf(ww), 0), DV - 1);
    const int lv = lab[(size_t)b * NVOX + (nd * DV + nh) * DV + nw];
    out_lab[vox] = (float)lv;
}

extern "C" void kernel_launch(void* const* d_in, const int* in_sizes, int n_in,
                              void* d_out, int out_size) {
    const float4* img    = (const float4*)d_in[0];  // [2,128,128,128,4] f32
    const int*    lab    = (const int*)d_in[1];     // [2,128,128,128,1] i32
    const float*  coarse = (const float*)d_in[2];   // [2,4,4,4,3] f32

    float* out   = (float*)d_out;
    float4* oimg = (float4*)out;
    float*  olab = out + (size_t)2 * IMG_FLOATS_PER_B;

    precompute_weights_kernel<<<1, 128>>>();
    resizeD_kernel<<<(2 * DV * 48 + 255) / 256, 256>>>(coarse);
    resizeH_kernel<<<(2 * DV * DV * 12 + 255) / 256, 256>>>();
    { dim3 g(DV, DV, 2); resizeW_kernel<<<g, 128>>>(); }
    { dim3 g(DV, 2);     gaussD_kernel<<<g, 384>>>(); }
    { dim3 g(DV, 2);     gaussH_kernel<<<g, 384>>>(); }
    { dim3 g(DV, DV, 2); warp_kernel<<<g, 128>>>(img, lab, oimg, olab); }
}

// round 7
// speedup vs baseline: 1.3150x; 1.3150x over previous
#include <cuda_runtime.h>
#include <math.h>

// RandomElasticDeformation3D — staged-f32 flow pipeline (bit-identical to the
// R6 passing version), restructured for parallelism:
//   K1 weights | K2 resizeD+resizeH | K3 resizeW+gaussD (d-chunked)
//   K4 gaussH (h-chunked) | K5 gaussW + warp
// All fma chains and per-stage f32 roundings are unchanged => same output bits.

#define DV 128
#define NVOX (DV * DV * DV)
#define IMG_FLOATS_PER_B (NVOX * 4)
#define ROWF (DV * 3)

static __device__ float4 g_A[DV];           // cubic resize rows (128 x 4)
static __device__ float  g_G[16];           // gaussian taps
static __device__ float  g_RH[2 * DV * DV * 4 * 3];          // [b,d,h,k,c]
static __device__ float  g_F1[(size_t)2 * DV * DV * DV * 3]; // after gauss D
static __device__ float  g_F2[(size_t)2 * DV * DV * DV * 3]; // after gauss H

// ---------------------------------------------------------------------------
__device__ __forceinline__ float keys_cubic_f32(float x) {
    float o = __fadd_rn(__fmul_rn(__fmul_rn(__fadd_rn(__fmul_rn(1.5f, x), -2.5f), x), x), 1.0f);
    if (x >= 1.0f)
        o = __fadd_rn(__fmul_rn(__fadd_rn(__fmul_rn(__fadd_rn(__fmul_rn(-0.5f, x), 2.5f), x), -4.0f), x), 2.0f);
    if (x >= 2.0f) o = 0.0f;
    return o;
}

__global__ void precompute_weights_kernel() {
    const int n = threadIdx.x;
    if (n < 16) {
        double ks = 0.0;
        for (int t = 0; t < 16; ++t) {
            double ax = (double)(t - 7);
            ks += exp(-ax * ax / 12.5);
        }
        double axn = (double)(n - 7);
        g_G[n] = (float)(exp(-axn * axn / 12.5) / ks);
    }
    if (n < DV) {
        float s = __fadd_rn(__fmul_rn(__fadd_rn((float)n, 0.5f), 0.03125f), -0.5f);
        float wv[4];
#pragma unroll
        for (int i = 0; i < 4; ++i) wv[i] = keys_cubic_f32(fabsf(__fadd_rn(s, -(float)i)));
        float tot = __fadd_rn(__fadd_rn(__fadd_rn(wv[0], wv[1]), wv[2]), wv[3]);
        g_A[n] = make_float4(__fdiv_rn(wv[0], tot), __fdiv_rn(wv[1], tot),
                             __fdiv_rn(wv[2], tot), __fdiv_rn(wv[3], tot));
    }
}

// ---------------------------------------------------------------------------
// K2: resize D then H.  grid(d, b), 128 threads (h).
// RD row computed into smem with the SAME fma chain as before, then RH.
// ---------------------------------------------------------------------------
__global__ void __launch_bounds__(128)
resizeDH_kernel(const float* __restrict__ coarse) {
    const int h = threadIdx.x;
    const int d = blockIdx.x;
    const int b = blockIdx.y;

    __shared__ float sRD[48];               // [j,k,c]
    if (threadIdx.x < 48) {
        const int c = threadIdx.x % 3;
        const int k = (threadIdx.x / 3) % 4;
        const int j = threadIdx.x / 12;
        const float4 A = g_A[d];
        const float Ai[4] = {A.x, A.y, A.z, A.w};
        float acc = 0.0f;
#pragma unroll
        for (int i = 0; i < 4; ++i)
            acc = fmaf(Ai[i], coarse[(((b * 4 + i) * 4 + j) * 4 + k) * 3 + c], acc);
        sRD[threadIdx.x] = acc;
    }
    __syncthreads();

    const float4 A = g_A[h];
    const float Aj[4] = {A.x, A.y, A.z, A.w};
    float* o = g_RH + ((b * DV + d) * DV + h) * 12;
#pragma unroll
    for (int r = 0; r < 12; ++r) {          // r = k*3+c
        float acc = 0.0f;
#pragma unroll
        for (int j = 0; j < 4; ++j)
            acc = fmaf(Aj[j], sRD[j * 12 + r], acc);
        o[r] = acc;
    }
}

// ---------------------------------------------------------------------------
// K3: resize W + gauss D fused, d-chunked.  grid(h, dchunk=4, b), 128 thr (w).
// R3[dp] recomputed on the fly from smem RH (same chain), 16-deep register
// shift window for the D gaussian. Bits identical to separate-kernel version.
// ---------------------------------------------------------------------------
#define D_CHUNK 32
__global__ void __launch_bounds__(128)
resizeW_gaussD_kernel() {
    const int w = threadIdx.x;
    const int h = blockIdx.x;
    const int d0 = blockIdx.y * D_CHUNK;
    const int b = blockIdx.z;

    __shared__ float sRH[DV * 12];          // RH[b, :, h, :, :]
    for (int t = threadIdx.x; t < DV * 12; t += 128)
        sRH[t] = g_RH[((b * DV) * DV + h) * 12 + (t / 12) * DV * 12 + (t % 12)];
    __syncthreads();

    const float4 A = g_A[w];
    const float Ak[4] = {A.x, A.y, A.z, A.w};
    float G[16];
#pragma unroll
    for (int t = 0; t < 16; ++t) G[t] = g_G[t];

    // R3[dp][c] with the exact resizeW fma chain
    auto r3 = [&](int dp, int c) -> float {
        float acc = 0.0f;
#pragma unroll
        for (int k = 0; k < 4; ++k)
            acc = fmaf(Ak[k], sRH[dp * 12 + k * 3 + c], acc);
        return acc;
    };

    float win0[16], win1[16], win2[16];
#pragma unroll
    for (int t = 0; t < 16; ++t) {
        const int dp = d0 + t - 7;
        const bool ok = (dp >= 0) && (dp < DV);
        win0[t] = ok ? r3(dp, 0) : 0.0f;
        win1[t] = ok ? r3(dp, 1) : 0.0f;
        win2[t] = ok ? r3(dp, 2) : 0.0f;
    }

    const size_t base = ((size_t)b * DV * DV + h) * ROWF + w * 3;
    for (int d = d0; d < d0 + D_CHUNK; ++d) {
        float a0 = 0.0f, a1 = 0.0f, a2 = 0.0f;
#pragma unroll
        for (int t = 0; t < 16; ++t) {
            a0 = fmaf(G[t], win0[t], a0);
            a1 = fmaf(G[t], win1[t], a1);
            a2 = fmaf(G[t], win2[t], a2);
        }
        float* o = g_F1 + base + (size_t)d * DV * ROWF / DV * DV; // (b,d,h,w,*)
        // simplify: base already has (b,*,h,w); d stride = DV*ROWF
        o = g_F1 + ((size_t)b * DV * DV + (size_t)d * DV + h) * ROWF + w * 3;
        o[0] = a0; o[1] = a1; o[2] = a2;
#pragma unroll
        for (int t = 0; t < 15; ++t) { win0[t] = win0[t + 1]; win1[t] = win1[t + 1]; win2[t] = win2[t + 1]; }
        const int nxt = d + 9;
        const bool ok = (nxt < DV);
        win0[15] = ok ? r3(nxt, 0) : 0.0f;
        win1[15] = ok ? r3(nxt, 1) : 0.0f;
        win2[15] = ok ? r3(nxt, 2) : 0.0f;
    }
}

// ---------------------------------------------------------------------------
// K4: gauss H, h-chunked.  grid(d, hchunk=4, b), 384 threads = (w,c).
// ---------------------------------------------------------------------------
#define H_CHUNK 32
__global__ void __launch_bounds__(384)
gaussH_kernel() {
    const int tid = threadIdx.x;
    const int d = blockIdx.x;
    const int h0 = blockIdx.y * H_CHUNK;
    const int b = blockIdx.z;
    float G[16];
#pragma unroll
    for (int t = 0; t < 16; ++t) G[t] = g_G[t];

    const size_t base = ((size_t)b * DV + d) * DV * ROWF + tid;
    const size_t hstr = (size_t)ROWF;

    float win[16];
#pragma unroll
    for (int t = 0; t < 16; ++t) {
        const int hp = h0 + t - 7;
        win[t] = (hp >= 0 && hp < DV) ? g_F1[base + (size_t)hp * hstr] : 0.0f;
    }

    for (int h = h0; h < h0 + H_CHUNK; ++h) {
        float acc = 0.0f;
#pragma unroll
        for (int t = 0; t < 16; ++t) acc = fmaf(G[t], win[t], acc);
        g_F2[base + (size_t)h * hstr] = acc;
#pragma unroll
        for (int t = 0; t < 15; ++t) win[t] = win[t + 1];
        const int nxt = h + 9;
        win[15] = (nxt < DV) ? g_F1[base + (size_t)nxt * hstr] : 0.0f;
    }
}

// ---------------------------------------------------------------------------
// K5: gauss W (pad_lo=7, pad_hi=8) + *ALPHA + trilinear/nearest warp.
// grid(h, d, b), 128 threads (w).  Unchanged from the passing R6 kernel.
// ---------------------------------------------------------------------------
__global__ void __launch_bounds__(128)
warp_kernel(const float4* __restrict__ img,
            const int*    __restrict__ lab,
            float4*       __restrict__ out_img,
            float*        __restrict__ out_lab) {
    const int w = threadIdx.x;
    const int h = blockIdx.x;
    const int d = blockIdx.y;
    const int b = blockIdx.z;

    __shared__ float row[(DV + 16) * 3];    // wp = -7..136 at (wp+7)*3+c
    if (threadIdx.x < 21) row[threadIdx.x] = 0.0f;
    if (threadIdx.x < 27) row[(DV + 7) * 3 + threadIdx.x] = 0.0f;
    {
        const float* src = g_F2 + (((size_t)b * DV + d) * DV + h) * ROWF;
#pragma unroll
        for (int t = 0; t < 3; ++t)
            row[21 + threadIdx.x + t * 128] = src[threadIdx.x + t * 128];
    }
    __syncthreads();

    float G[16];
#pragma unroll
    for (int t = 0; t < 16; ++t) G[t] = g_G[t];

    float fl[3];
#pragma unroll
    for (int c = 0; c < 3; ++c) {
        float acc = 0.0f;
#pragma unroll
        for (int t = 0; t < 16; ++t)
            acc = fmaf(G[t], row[(w + t) * 3 + c], acc);
        fl[c] = __fmul_rn(acc, 35.0f);
    }

    const float wd = __fadd_rn((float)d, fl[0]);
    const float wh = __fadd_rn((float)h, fl[1]);
    const float ww = __fadd_rn((float)w, fl[2]);

    const float fdd = floorf(wd), fhh = floorf(wh), fww = floorf(ww);
    const float td = wd - fdd, th = wh - fhh, tw = ww - fww;

    const int d0 = min(max((int)fdd,     0), DV - 1);
    const int d1 = min(max((int)fdd + 1, 0), DV - 1);
    const int h0 = min(max((int)fhh,     0), DV - 1);
    const int h1 = min(max((int)fhh + 1, 0), DV - 1);
    const int w0 = min(max((int)fww,     0), DV - 1);
    const int w1 = min(max((int)fww + 1, 0), DV - 1);

    const float4* ib = img + (size_t)b * NVOX;
    const float4 v000 = ib[(d0 * DV + h0) * DV + w0];
    const float4 v001 = ib[(d0 * DV + h0) * DV + w1];
    const float4 v010 = ib[(d0 * DV + h1) * DV + w0];
    const float4 v011 = ib[(d0 * DV + h1) * DV + w1];
    const float4 v100 = ib[(d1 * DV + h0) * DV + w0];
    const float4 v101 = ib[(d1 * DV + h0) * DV + w1];
    const float4 v110 = ib[(d1 * DV + h1) * DV + w0];
    const float4 v111 = ib[(d1 * DV + h1) * DV + w1];

    const float omtw = 1.0f - tw, omth = 1.0f - th, omtd = 1.0f - td;
    float4 r;
    {
        float c00, c01, c10, c11, c0, c1;
        c00 = v000.x * omtw + v001.x * tw;  c01 = v010.x * omtw + v011.x * tw;
        c10 = v100.x * omtw + v101.x * tw;  c11 = v110.x * omtw + v111.x * tw;
        c0 = c00 * omth + c01 * th;  c1 = c10 * omth + c11 * th;
        r.x = c0 * omtd + c1 * td;
        c00 = v000.y * omtw + v001.y * tw;  c01 = v010.y * omtw + v011.y * tw;
        c10 = v100.y * omtw + v101.y * tw;  c11 = v110.y * omtw + v111.y * tw;
        c0 = c00 * omth + c01 * th;  c1 = c10 * omth + c11 * th;
        r.y = c0 * omtd + c1 * td;
        c00 = v000.z * omtw + v001.z * tw;  c01 = v010.z * omtw + v011.z * tw;
        c10 = v100.z * omtw + v101.z * tw;  c11 = v110.z * omtw + v111.z * tw;
        c0 = c00 * omth + c01 * th;  c1 = c10 * omth + c11 * th;
        r.z = c0 * omtd + c1 * td;
        c00 = v000.w * omtw + v001.w * tw;  c01 = v010.w * omtw + v011.w * tw;
        c10 = v100.w * omtw + v101.w * tw;  c11 = v110.w * omtw + v111.w * tw;
        c0 = c00 * omth + c01 * th;  c1 = c10 * omth + c11 * th;
        r.w = c0 * omtd + c1 * td;
    }

    const int vox = ((b * DV + d) * DV + h) * DV + w;
    out_img[vox] = r;

    const int nd = min(max((int)rintf(wd), 0), DV - 1);
    const int nh = min(max((int)rintf(wh), 0), DV - 1);
    const int nw = min(max((int)rintf(ww), 0), DV - 1);
    const int lv = lab[(size_t)b * NVOX + (nd * DV + nh) * DV + nw];
    out_lab[vox] = (float)lv;
}

extern "C" void kernel_launch(void* const* d_in, const int* in_sizes, int n_in,
                              void* d_out, int out_size) {
    const float4* img    = (const float4*)d_in[0];
    const int*    lab    = (const int*)d_in[1];
    const float*  coarse = (const float*)d_in[2];

    float* out   = (float*)d_out;
    float4* oimg = (float4*)out;
    float*  olab = out + (size_t)2 * IMG_FLOATS_PER_B;

    precompute_weights_kernel<<<1, 128>>>();
    { dim3 g(DV, 2);                      resizeDH_kernel<<<g, 128>>>(coarse); }
    { dim3 g(DV, DV / D_CHUNK, 2);        resizeW_gaussD_kernel<<<g, 128>>>(); }
    { dim3 g(DV, DV / H_CHUNK, 2);        gaussH_kernel<<<g, 384>>>(); }
    { dim3 g(DV, DV, 2);                  warp_kernel<<<g, 128>>>(img, lab, oimg, olab); }
}

// round 10
// speedup vs baseline: 1.4165x; 1.0772x over previous
#include <cuda_runtime.h>
#include <math.h>

// RandomElasticDeformation3D — staged-f32 flow pipeline (bit-identical chains):
//   K1 weights | K2 resizeD+resizeH | K3 resizeW+gaussD (d-chunked)
//   K4 gaussH (chunk-batched loads, MLP~31) | K5 gaussW + warp
// All fma chains and per-stage f32 roundings unchanged => same output bits.

#define DV 128
#define NVOX (DV * DV * DV)
#define IMG_FLOATS_PER_B (NVOX * 4)
#define ROWF (DV * 3)

static __device__ float4 g_A[DV];           // cubic resize rows (128 x 4)
static __device__ float  g_G[16];           // gaussian taps
static __device__ float  g_RH[2 * DV * DV * 4 * 3];          // [b,d,h,k,c]
static __device__ float  g_F1[(size_t)2 * DV * DV * DV * 3]; // after gauss D
static __device__ float  g_F2[(size_t)2 * DV * DV * DV * 3]; // after gauss H

// ---------------------------------------------------------------------------
__device__ __forceinline__ float keys_cubic_f32(float x) {
    float o = __fadd_rn(__fmul_rn(__fmul_rn(__fadd_rn(__fmul_rn(1.5f, x), -2.5f), x), x), 1.0f);
    if (x >= 1.0f)
        o = __fadd_rn(__fmul_rn(__fadd_rn(__fmul_rn(__fadd_rn(__fmul_rn(-0.5f, x), 2.5f), x), -4.0f), x), 2.0f);
    if (x >= 2.0f) o = 0.0f;
    return o;
}

__global__ void precompute_weights_kernel() {
    const int n = threadIdx.x;
    if (n < 16) {
        double ks = 0.0;
        for (int t = 0; t < 16; ++t) {
            double ax = (double)(t - 7);
            ks += exp(-ax * ax / 12.5);
        }
        double axn = (double)(n - 7);
        g_G[n] = (float)(exp(-axn * axn / 12.5) / ks);
    }
    if (n < DV) {
        float s = __fadd_rn(__fmul_rn(__fadd_rn((float)n, 0.5f), 0.03125f), -0.5f);
        float wv[4];
#pragma unroll
        for (int i = 0; i < 4; ++i) wv[i] = keys_cubic_f32(fabsf(__fadd_rn(s, -(float)i)));
        float tot = __fadd_rn(__fadd_rn(__fadd_rn(wv[0], wv[1]), wv[2]), wv[3]);
        g_A[n] = make_float4(__fdiv_rn(wv[0], tot), __fdiv_rn(wv[1], tot),
                             __fdiv_rn(wv[2], tot), __fdiv_rn(wv[3], tot));
    }
}

// ---------------------------------------------------------------------------
// K2: resize D then H.  grid(d, b), 128 threads (h).
// ---------------------------------------------------------------------------
__global__ void __launch_bounds__(128)
resizeDH_kernel(const float* __restrict__ coarse) {
    const int h = threadIdx.x;
    const int d = blockIdx.x;
    const int b = blockIdx.y;

    __shared__ float sRD[48];               // [j,k,c]
    if (threadIdx.x < 48) {
        const int c = threadIdx.x % 3;
        const int k = (threadIdx.x / 3) % 4;
        const int j = threadIdx.x / 12;
        const float4 A = g_A[d];
        const float Ai[4] = {A.x, A.y, A.z, A.w};
        float acc = 0.0f;
#pragma unroll
        for (int i = 0; i < 4; ++i)
            acc = fmaf(Ai[i], coarse[(((b * 4 + i) * 4 + j) * 4 + k) * 3 + c], acc);
        sRD[threadIdx.x] = acc;
    }
    __syncthreads();

    const float4 A = g_A[h];
    const float Aj[4] = {A.x, A.y, A.z, A.w};
    float* o = g_RH + ((b * DV + d) * DV + h) * 12;
#pragma unroll
    for (int r = 0; r < 12; ++r) {
        float acc = 0.0f;
#pragma unroll
        for (int j = 0; j < 4; ++j)
            acc = fmaf(Aj[j], sRD[j * 12 + r], acc);
        o[r] = acc;
    }
}

// ---------------------------------------------------------------------------
// K3: resize W + gauss D fused, d-chunked.  grid(h, 4, b), 128 thr (w).
// ---------------------------------------------------------------------------
#define D_CHUNK 32
__global__ void __launch_bounds__(128)
resizeW_gaussD_kernel() {
    const int w = threadIdx.x;
    const int h = blockIdx.x;
    const int d0 = blockIdx.y * D_CHUNK;
    const int b = blockIdx.z;

    __shared__ float sRH[DV * 12];          // RH[b, :, h, :, :]
    for (int t = threadIdx.x; t < DV * 12; t += 128)
        sRH[t] = g_RH[((b * DV) * DV + h) * 12 + (t / 12) * DV * 12 + (t % 12)];
    __syncthreads();

    const float4 A = g_A[w];
    const float Ak[4] = {A.x, A.y, A.z, A.w};
    float G[16];
#pragma unroll
    for (int t = 0; t < 16; ++t) G[t] = g_G[t];

    auto r3 = [&](int dp, int c) -> float {
        float acc = 0.0f;
#pragma unroll
        for (int k = 0; k < 4; ++k)
            acc = fmaf(Ak[k], sRH[dp * 12 + k * 3 + c], acc);
        return acc;
    };

    float win0[16], win1[16], win2[16];
#pragma unroll
    for (int t = 0; t < 16; ++t) {
        const int dp = d0 + t - 7;
        const bool ok = (dp >= 0) && (dp < DV);
        win0[t] = ok ? r3(dp, 0) : 0.0f;
        win1[t] = ok ? r3(dp, 1) : 0.0f;
        win2[t] = ok ? r3(dp, 2) : 0.0f;
    }

    for (int d = d0; d < d0 + D_CHUNK; ++d) {
        float a0 = 0.0f, a1 = 0.0f, a2 = 0.0f;
#pragma unroll
        for (int t = 0; t < 16; ++t) {
            a0 = fmaf(G[t], win0[t], a0);
            a1 = fmaf(G[t], win1[t], a1);
            a2 = fmaf(G[t], win2[t], a2);
        }
        float* o = g_F1 + ((size_t)b * DV * DV + (size_t)d * DV + h) * ROWF + w * 3;
        o[0] = a0; o[1] = a1; o[2] = a2;
#pragma unroll
        for (int t = 0; t < 15; ++t) { win0[t] = win0[t + 1]; win1[t] = win1[t + 1]; win2[t] = win2[t + 1]; }
        const int nxt = d + 9;
        const bool ok = (nxt < DV);
        win0[15] = ok ? r3(nxt, 0) : 0.0f;
        win1[15] = ok ? r3(nxt, 1) : 0.0f;
        win2[15] = ok ? r3(nxt, 2) : 0.0f;
    }
}

// ---------------------------------------------------------------------------
// K4: gauss H, chunk of 16 outputs per block; ALL 31 inputs loaded upfront
// (MLP ~31), then a dependency-free FMA block. grid(d, 8, b), 384 thr (w,c).
// Per-output fma chain identical to before => same bits.
// ---------------------------------------------------------------------------
#define H_CHUNK 16
__global__ void __launch_bounds__(384)
gaussH_kernel() {
    const int tid = threadIdx.x;
    const int d = blockIdx.x;
    const int h0 = blockIdx.y * H_CHUNK;
    const int b = blockIdx.z;

    float G[16];
#pragma unroll
    for (int t = 0; t < 16; ++t) G[t] = g_G[t];

    const size_t rowbase = ((size_t)b * DV + d) * DV * ROWF + tid;

    // inputs h0-7 .. h0+23  (31 values), all loads independent
    float x[31];
#pragma unroll
    for (int t = 0; t < 31; ++t) {
        const int hp = h0 + t - 7;
        x[t] = (hp >= 0 && hp < DV) ? g_F1[rowbase + (size_t)hp * ROWF] : 0.0f;
    }

#pragma unroll
    for (int i = 0; i < H_CHUNK; ++i) {
        float acc = 0.0f;
#pragma unroll
        for (int t = 0; t < 16; ++t)
            acc = fmaf(G[t], x[i + t], acc);
        g_F2[rowbase + (size_t)(h0 + i) * ROWF] = acc;
    }
}

// ---------------------------------------------------------------------------
// K5: gauss W (pad_lo=7, pad_hi=8) + *ALPHA + trilinear/nearest warp.
// grid(h, d, b), 128 threads (w).
// ---------------------------------------------------------------------------
__global__ void __launch_bounds__(128)
warp_kernel(const float4* __restrict__ img,
            const int*    __restrict__ lab,
            float4*       __restrict__ out_img,
            float*        __restrict__ out_lab) {
    const int w = threadIdx.x;
    const int h = blockIdx.x;
    const int d = blockIdx.y;
    const int b = blockIdx.z;

    __shared__ float row[(DV + 16) * 3];    // wp = -7..136 at (wp+7)*3+c
    if (threadIdx.x < 21) row[threadIdx.x] = 0.0f;
    if (threadIdx.x < 27) row[(DV + 7) * 3 + threadIdx.x] = 0.0f;
    {
        const float* src = g_F2 + (((size_t)b * DV + d) * DV + h) * ROWF;
#pragma unroll
        for (int t = 0; t < 3; ++t)
            row[21 + threadIdx.x + t * 128] = src[threadIdx.x + t * 128];
    }
    __syncthreads();

    float G[16];
#pragma unroll
    for (int t = 0; t < 16; ++t) G[t] = g_G[t];

    float fl[3];
#pragma unroll
    for (int c = 0; c < 3; ++c) {
        float acc = 0.0f;
#pragma unroll
        for (int t = 0; t < 16; ++t)
            acc = fmaf(G[t], row[(w + t) * 3 + c], acc);
        fl[c] = __fmul_rn(acc, 35.0f);
    }

    const float wd = __fadd_rn((float)d, fl[0]);
    const float wh = __fadd_rn((float)h, fl[1]);
    const float ww = __fadd_rn((float)w, fl[2]);

    const float fdd = floorf(wd), fhh = floorf(wh), fww = floorf(ww);
    const float td = wd - fdd, th = wh - fhh, tw = ww - fww;

    const int d0 = min(max((int)fdd,     0), DV - 1);
    const int d1 = min(max((int)fdd + 1, 0), DV - 1);
    const int h0 = min(max((int)fhh,     0), DV - 1);
    const int h1 = min(max((int)fhh + 1, 0), DV - 1);
    const int w0 = min(max((int)fww,     0), DV - 1);
    const int w1 = min(max((int)fww + 1, 0), DV - 1);

    const float4* ib = img + (size_t)b * NVOX;
    const float4 v000 = ib[(d0 * DV + h0) * DV + w0];
    const float4 v001 = ib[(d0 * DV + h0) * DV + w1];
    const float4 v010 = ib[(d0 * DV + h1) * DV + w0];
    const float4 v011 = ib[(d0 * DV + h1) * DV + w1];
    const float4 v100 = ib[(d1 * DV + h0) * DV + w0];
    const float4 v101 = ib[(d1 * DV + h0) * DV + w1];
    const float4 v110 = ib[(d1 * DV + h1) * DV + w0];
    const float4 v111 = ib[(d1 * DV + h1) * DV + w1];

    const float omtw = 1.0f - tw, omth = 1.0f - th, omtd = 1.0f - td;
    float4 r;
    {
        float c00, c01, c10, c11, c0, c1;
        c00 = v000.x * omtw + v001.x * tw;  c01 = v010.x * omtw + v011.x * tw;
        c10 = v100.x * omtw + v101.x * tw;  c11 = v110.x * omtw + v111.x * tw;
        c0 = c00 * omth + c01 * th;  c1 = c10 * omth + c11 * th;
        r.x = c0 * omtd + c1 * td;
        c00 = v000.y * omtw + v001.y * tw;  c01 = v010.y * omtw + v011.y * tw;
        c10 = v100.y * omtw + v101.y * tw;  c11 = v110.y * omtw + v111.y * tw;
        c0 = c00 * omth + c01 * th;  c1 = c10 * omth + c11 * th;
        r.y = c0 * omtd + c1 * td;
        c00 = v000.z * omtw + v001.z * tw;  c01 = v010.z * omtw + v011.z * tw;
        c10 = v100.z * omtw + v101.z * tw;  c11 = v110.z * omtw + v111.z * tw;
        c0 = c00 * omth + c01 * th;  c1 = c10 * omth + c11 * th;
        r.z = c0 * omtd + c1 * td;
        c00 = v000.w * omtw + v001.w * tw;  c01 = v010.w * omtw + v011.w * tw;
        c10 = v100.w * omtw + v101.w * tw;  c11 = v110.w * omtw + v111.w * tw;
        c0 = c00 * omth + c01 * th;  c1 = c10 * omth + c11 * th;
        r.w = c0 * omtd + c1 * td;
    }

    const int vox = ((b * DV + d) * DV + h) * DV + w;
    out_img[vox] = r;

    const int nd = min(max((int)rintf(wd), 0), DV - 1);
    const int nh = min(max((int)rintf(wh), 0), DV - 1);
    const int nw = min(max((int)rintf(ww), 0), DV - 1);
    const int lv = lab[(size_t)b * NVOX + (nd * DV + nh) * DV + nw];
    out_lab[vox] = (float)lv;
}

extern "C" void kernel_launch(void* const* d_in, const int* in_sizes, int n_in,
                              void* d_out, int out_size) {
    const float4* img    = (const float4*)d_in[0];
    const int*    lab    = (const int*)d_in[1];
    const float*  coarse = (const float*)d_in[2];

    float* out   = (float*)d_out;
    float4* oimg = (float4*)out;
    float*  olab = out + (size_t)2 * IMG_FLOATS_PER_B;

    precompute_weights_kernel<<<1, 128>>>();
    { dim3 g(DV, 2);                      resizeDH_kernel<<<g, 128>>>(coarse); }
    { dim3 g(DV, DV / D_CHUNK, 2);        resizeW_gaussD_kernel<<<g, 128>>>(); }
    { dim3 g(DV, DV / H_CHUNK, 2);        gaussH_kernel<<<g, 384>>>(); }
    { dim3 g(DV, DV, 2);                  warp_kernel<<<g, 128>>>(img, lab, oimg, olab); }
}

// round 12
// speedup vs baseline: 1.4987x; 1.0580x over previous
#include <cuda_runtime.h>
#include <math.h>

// RandomElasticDeformation3D — staged-f32 flow pipeline (bit-identical chains):
//   K1 weights | K2 resizeD+resizeH | K3 resizeW+gaussD (d-chunked)
//   K4 gaussH+gaussW+warp fused (F2 eliminated)
// All fma chains and per-stage f32 roundings unchanged => same output bits.

#define DV 128
#define NVOX (DV * DV * DV)
#define IMG_FLOATS_PER_B (NVOX * 4)
#define ROWF (DV * 3)

static __device__ float4 g_A[DV];           // cubic resize rows (128 x 4)
static __device__ float  g_G[16];           // gaussian taps
static __device__ float  g_RH[2 * DV * DV * 4 * 3];          // [b,d,h,k,c]
static __device__ float  g_F1[(size_t)2 * DV * DV * DV * 3]; // after gauss D

// ---------------------------------------------------------------------------
__device__ __forceinline__ float keys_cubic_f32(float x) {
    float o = __fadd_rn(__fmul_rn(__fmul_rn(__fadd_rn(__fmul_rn(1.5f, x), -2.5f), x), x), 1.0f);
    if (x >= 1.0f)
        o = __fadd_rn(__fmul_rn(__fadd_rn(__fmul_rn(__fadd_rn(__fmul_rn(-0.5f, x), 2.5f), x), -4.0f), x), 2.0f);
    if (x >= 2.0f) o = 0.0f;
    return o;
}

__global__ void precompute_weights_kernel() {
    const int n = threadIdx.x;
    if (n < 16) {
        double ks = 0.0;
        for (int t = 0; t < 16; ++t) {
            double ax = (double)(t - 7);
            ks += exp(-ax * ax / 12.5);
        }
        double axn = (double)(n - 7);
        g_G[n] = (float)(exp(-axn * axn / 12.5) / ks);
    }
    if (n < DV) {
        float s = __fadd_rn(__fmul_rn(__fadd_rn((float)n, 0.5f), 0.03125f), -0.5f);
        float wv[4];
#pragma unroll
        for (int i = 0; i < 4; ++i) wv[i] = keys_cubic_f32(fabsf(__fadd_rn(s, -(float)i)));
        float tot = __fadd_rn(__fadd_rn(__fadd_rn(wv[0], wv[1]), wv[2]), wv[3]);
        g_A[n] = make_float4(__fdiv_rn(wv[0], tot), __fdiv_rn(wv[1], tot),
                             __fdiv_rn(wv[2], tot), __fdiv_rn(wv[3], tot));
    }
}

// ---------------------------------------------------------------------------
// K2: resize D then H.  grid(d, b), 128 threads (h).
// ---------------------------------------------------------------------------
__global__ void __launch_bounds__(128)
resizeDH_kernel(const float* __restrict__ coarse) {
    const int h = threadIdx.x;
    const int d = blockIdx.x;
    const int b = blockIdx.y;

    __shared__ float sRD[48];               // [j,k,c]
    if (threadIdx.x < 48) {
        const int c = threadIdx.x % 3;
        const int k = (threadIdx.x / 3) % 4;
        const int j = threadIdx.x / 12;
        const float4 A = g_A[d];
        const float Ai[4] = {A.x, A.y, A.z, A.w};
        float acc = 0.0f;
#pragma unroll
        for (int i = 0; i < 4; ++i)
            acc = fmaf(Ai[i], coarse[(((b * 4 + i) * 4 + j) * 4 + k) * 3 + c], acc);
        sRD[threadIdx.x] = acc;
    }
    __syncthreads();

    const float4 A = g_A[h];
    const float Aj[4] = {A.x, A.y, A.z, A.w};
    float* o = g_RH + ((b * DV + d) * DV + h) * 12;
#pragma unroll
    for (int r = 0; r < 12; ++r) {
        float acc = 0.0f;
#pragma unroll
        for (int j = 0; j < 4; ++j)
            acc = fmaf(Aj[j], sRD[j * 12 + r], acc);
        o[r] = acc;
    }
}

// ---------------------------------------------------------------------------
// K3: resize W + gauss D fused, d-chunked.  grid(h, 4, b), 128 thr (w).
// ---------------------------------------------------------------------------
#define D_CHUNK 32
__global__ void __launch_bounds__(128)
resizeW_gaussD_kernel() {
    const int w = threadIdx.x;
    const int h = blockIdx.x;
    const int d0 = blockIdx.y * D_CHUNK;
    const int b = blockIdx.z;

    __shared__ float sRH[DV * 12];          // RH[b, :, h, :, :]
    for (int t = threadIdx.x; t < DV * 12; t += 128)
        sRH[t] = g_RH[((b * DV) * DV + h) * 12 + (t / 12) * DV * 12 + (t % 12)];
    __syncthreads();

    const float4 A = g_A[w];
    const float Ak[4] = {A.x, A.y, A.z, A.w};
    float G[16];
#pragma unroll
    for (int t = 0; t < 16; ++t) G[t] = g_G[t];

    auto r3 = [&](int dp, int c) -> float {
        float acc = 0.0f;
#pragma unroll
        for (int k = 0; k < 4; ++k)
            acc = fmaf(Ak[k], sRH[dp * 12 + k * 3 + c], acc);
        return acc;
    };

    float win0[16], win1[16], win2[16];
#pragma unroll
    for (int t = 0; t < 16; ++t) {
        const int dp = d0 + t - 7;
        const bool ok = (dp >= 0) && (dp < DV);
        win0[t] = ok ? r3(dp, 0) : 0.0f;
        win1[t] = ok ? r3(dp, 1) : 0.0f;
        win2[t] = ok ? r3(dp, 2) : 0.0f;
    }

    for (int d = d0; d < d0 + D_CHUNK; ++d) {
        float a0 = 0.0f, a1 = 0.0f, a2 = 0.0f;
#pragma unroll
        for (int t = 0; t < 16; ++t) {
            a0 = fmaf(G[t], win0[t], a0);
            a1 = fmaf(G[t], win1[t], a1);
            a2 = fmaf(G[t], win2[t], a2);
        }
        float* o = g_F1 + ((size_t)b * DV * DV + (size_t)d * DV + h) * ROWF + w * 3;
        o[0] = a0; o[1] = a1; o[2] = a2;
#pragma unroll
        for (int t = 0; t < 15; ++t) { win0[t] = win0[t + 1]; win1[t] = win1[t + 1]; win2[t] = win2[t + 1]; }
        const int nxt = d + 9;
        const bool ok = (nxt < DV);
        win0[15] = ok ? r3(nxt, 0) : 0.0f;
        win1[15] = ok ? r3(nxt, 1) : 0.0f;
        win2[15] = ok ? r3(nxt, 2) : 0.0f;
    }
}

// ---------------------------------------------------------------------------
// K4: gaussH + gaussW + warp fused.  grid(H/16, d, b), 128 threads (w).
// Per-thread 16-deep register rolling window over h (3 columns: c=0..2)
// computes the gaussH row bit-identically; row goes to smem; then the
// unchanged gaussW + warp code runs for that h. F2 never materialized.
// ---------------------------------------------------------------------------
#define H_TILE 16
__global__ void __launch_bounds__(128)
warp_fused_kernel(const float4* __restrict__ img,
                  const int*    __restrict__ lab,
                  float4*       __restrict__ out_img,
                  float*        __restrict__ out_lab) {
    const int w  = threadIdx.x;
    const int h0 = blockIdx.x * H_TILE;
    const int d  = blockIdx.y;
    const int b  = blockIdx.z;

    // row stores wp = -7..136 at (wp+7)*3+c  =>  (DV+16)*3 = 432 floats.
    __shared__ float row[(DV + 16) * 3];
    if (threadIdx.x < 21) row[threadIdx.x] = 0.0f;                 // wp = -7..-1
    if (threadIdx.x < 27) row[(DV + 7) * 3 + threadIdx.x] = 0.0f;  // wp = 128..136

    float G[16];
#pragma unroll
    for (int t = 0; t < 16; ++t) G[t] = g_G[t];

    // F1 element address for (b, d, hp, w, c):
    const size_t colbase = ((size_t)b * DV + d) * DV * ROWF + w * 3;

    // rolling window over h: win[c][t] == F1[h0 + i + t - 7] (i = current)
    float win0[16], win1[16], win2[16];
#pragma unroll
    for (int t = 0; t < 16; ++t) {
        const int hp = h0 + t - 7;
        const bool ok = (hp >= 0) && (hp < DV);
        const float* src = g_F1 + colbase + (size_t)hp * ROWF;
        win0[t] = ok ? src[0] : 0.0f;
        win1[t] = ok ? src[1] : 0.0f;
        win2[t] = ok ? src[2] : 0.0f;
    }

    const float4* ib = img + (size_t)b * NVOX;

    for (int i = 0; i < H_TILE; ++i) {
        const int h = h0 + i;

        // ---- gaussH for this thread's 3 columns (bit-identical chain) ----
        float f20 = 0.0f, f21 = 0.0f, f22 = 0.0f;
#pragma unroll
        for (int t = 0; t < 16; ++t) {
            f20 = fmaf(G[t], win0[t], f20);
            f21 = fmaf(G[t], win1[t], f21);
            f22 = fmaf(G[t], win2[t], f22);
        }

        // prefetch next h row (consumed after the second barrier)
        float nx0 = 0.0f, nx1 = 0.0f, nx2 = 0.0f;
        {
            const int hp = h + 9;
            if (hp < DV) {
                const float* src = g_F1 + colbase + (size_t)hp * ROWF;
                nx0 = src[0]; nx1 = src[1]; nx2 = src[2];
            }
        }

        row[21 + w * 3 + 0] = f20;
        row[21 + w * 3 + 1] = f21;
        row[21 + w * 3 + 2] = f22;
        __syncthreads();

        // ---- gaussW + *ALPHA (unchanged) ----
        float fl[3];
#pragma unroll
        for (int c = 0; c < 3; ++c) {
            float acc = 0.0f;
#pragma unroll
            for (int t = 0; t < 16; ++t)
                acc = fmaf(G[t], row[(w + t) * 3 + c], acc);
            fl[c] = __fmul_rn(acc, 35.0f);
        }

        const float wd = __fadd_rn((float)d, fl[0]);
        const float wh = __fadd_rn((float)h, fl[1]);
        const float ww = __fadd_rn((float)w, fl[2]);

        const float fdd = floorf(wd), fhh = floorf(wh), fww = floorf(ww);
        const float td = wd - fdd, th = wh - fhh, tw = ww - fww;

        const int d0i = min(max((int)fdd,     0), DV - 1);
        const int d1i = min(max((int)fdd + 1, 0), DV - 1);
        const int h0i = min(max((int)fhh,     0), DV - 1);
        const int h1i = min(max((int)fhh + 1, 0), DV - 1);
        const int w0i = min(max((int)fww,     0), DV - 1);
        const int w1i = min(max((int)fww + 1, 0), DV - 1);

        const float4 v000 = ib[(d0i * DV + h0i) * DV + w0i];
        const float4 v001 = ib[(d0i * DV + h0i) * DV + w1i];
        const float4 v010 = ib[(d0i * DV + h1i) * DV + w0i];
        const float4 v011 = ib[(d0i * DV + h1i) * DV + w1i];
        const float4 v100 = ib[(d1i * DV + h0i) * DV + w0i];
        const float4 v101 = ib[(d1i * DV + h0i) * DV + w1i];
        const float4 v110 = ib[(d1i * DV + h1i) * DV + w0i];
        const float4 v111 = ib[(d1i * DV + h1i) * DV + w1i];

        const float omtw = 1.0f - tw, omth = 1.0f - th, omtd = 1.0f - td;
        float4 r;
        {
            float c00, c01, c10, c11, c0, c1;
            c00 = v000.x * omtw + v001.x * tw;  c01 = v010.x * omtw + v011.x * tw;
            c10 = v100.x * omtw + v101.x * tw;  c11 = v110.x * omtw + v111.x * tw;
            c0 = c00 * omth + c01 * th;  c1 = c10 * omth + c11 * th;
            r.x = c0 * omtd + c1 * td;
            c00 = v000.y * omtw + v001.y * tw;  c01 = v010.y * omtw + v011.y * tw;
            c10 = v100.y * omtw + v101.y * tw;  c11 = v110.y * omtw + v111.y * tw;
            c0 = c00 * omth + c01 * th;  c1 = c10 * omth + c11 * th;
            r.y = c0 * omtd + c1 * td;
            c00 = v000.z * omtw + v001.z * tw;  c01 = v010.z * omtw + v011.z * tw;
            c10 = v100.z * omtw + v101.z * tw;  c11 = v110.z * omtw + v111.z * tw;
            c0 = c00 * omth + c01 * th;  c1 = c10 * omth + c11 * th;
            r.z = c0 * omtd + c1 * td;
            c00 = v000.w * omtw + v001.w * tw;  c01 = v010.w * omtw + v011.w * tw;
            c10 = v100.w * omtw + v101.w * tw;  c11 = v110.w * omtw + v111.w * tw;
            c0 = c00 * omth + c01 * th;  c1 = c10 * omth + c11 * th;
            r.w = c0 * omtd + c1 * td;
        }

        const int vox = ((b * DV + d) * DV + h) * DV + w;
        out_img[vox] = r;

        const int nd = min(max((int)rintf(wd), 0), DV - 1);
        const int nh = min(max((int)rintf(wh), 0), DV - 1);
        const int nw = min(max((int)rintf(ww), 0), DV - 1);
        const int lv = lab[(size_t)b * NVOX + (nd * DV + nh) * DV + nw];
        out_lab[vox] = (float)lv;

        __syncthreads();   // row[] reused next iteration

        // shift rolling window, insert prefetched row
#pragma unroll
        for (int t = 0; t < 15; ++t) { win0[t] = win0[t + 1]; win1[t] = win1[t + 1]; win2[t] = win2[t + 1]; }
        win0[15] = nx0; win1[15] = nx1; win2[15] = nx2;
    }
}

extern "C" void kernel_launch(void* const* d_in, const int* in_sizes, int n_in,
                              void* d_out, int out_size) {
    const float4* img    = (const float4*)d_in[0];
    const int*    lab    = (const int*)d_in[1];
    const float*  coarse = (const float*)d_in[2];

    float* out   = (float*)d_out;
    float4* oimg = (float4*)out;
    float*  olab = out + (size_t)2 * IMG_FLOATS_PER_B;

    precompute_weights_kernel<<<1, 128>>>();
    { dim3 g(DV, 2);                 resizeDH_kernel<<<g, 128>>>(coarse); }
    { dim3 g(DV, DV / D_CHUNK, 2);   resizeW_gaussD_kernel<<<g, 128>>>(); }
    { dim3 g(DV / H_TILE, DV, 2);    warp_fused_kernel<<<g, 128>>>(img, lab, oimg, olab); }
}